// round 5
// baseline (speedup 1.0000x reference)
#include <cuda_runtime.h>
#include <cstdint>

// ---------------- problem constants (fixed-shape problem) ----------------
constexpr int NN   = 10000;  // nodes
constexpr int F1   = 64;     // hidden feat
constexpr int COUT = 16;     // classes

// GEMM1 tiling
constexpr int BM = 128;
constexpr int BN = 64;
constexpr int BK = 8;
constexpr int KSPLIT = 8;
constexpr int NCHUNK = NN / BK;      // 1250 (exact)
constexpr int AS_LD  = 132;          // padded As row stride (floats)

// ---------------- device scratch (no allocation; NEVER passed from host) --
__device__ __align__(16) float g_deg[NN];
__device__ __align__(16) float g_dinv[NN];
__device__ __align__(16) float g_bufA[(size_t)NN * F1];          // GEMM outputs
__device__ __align__(16) float g_bufB[(size_t)NN * F1];          // aggregation outputs
__device__ __align__(16) float g_part[(size_t)KSPLIT * NN * F1]; // split-K partials

__device__ __forceinline__ int clampN(int v) {
    v = v < 0 ? 0 : v;
    return v < NN ? v : NN - 1;
}

// ---------------- packed f32x2 helpers ----------------
__device__ __forceinline__ unsigned long long pack2(float lo, float hi) {
    unsigned long long r;
    asm("mov.b64 %0, {%1, %2};" : "=l"(r) : "f"(lo), "f"(hi));
    return r;
}
__device__ __forceinline__ void ffma2(unsigned long long& d,
                                      unsigned long long a,
                                      unsigned long long b) {
    asm("fma.rn.f32x2 %0, %1, %2, %0;" : "+l"(d) : "l"(a), "l"(b));
}
__device__ __forceinline__ float2 unpack2(unsigned long long v) {
    float2 f;
    asm("mov.b64 {%0, %1}, %2;" : "=f"(f.x), "=f"(f.y) : "l"(v));
    return f;
}

// ---------------- degree / norm ----------------
__global__ void deg_init_kernel() {
    int i = blockIdx.x * blockDim.x + threadIdx.x;
    if (i < NN) g_deg[i] = 1.0f;  // self-loop
}

// edge_index is INT32 (JAX x64 disabled downgrades int64 -> int32)
__global__ void deg_count_kernel(const int* __restrict__ ei, int E) {
    int e = blockIdx.x * blockDim.x + threadIdx.x;
    if (e < E) {
        int dst = clampN(ei[E + e]);
        atomicAdd(&g_deg[dst], 1.0f);
    }
}

__global__ void dinv_kernel() {
    int i = blockIdx.x * blockDim.x + threadIdx.x;
    if (i < NN) g_dinv[i] = rsqrtf(g_deg[i]);  // deg >= 1 always
}

// ---------------- GEMM1: [NN, NN] x [NN, 64] -> g_part (split-K) ----------
// 128 threads, 8x8 micro-tile via packed fma.rn.f32x2, double-buffered SMEM.
__global__ void __launch_bounds__(128, 4) gemm1_kernel(const float* __restrict__ A,
                                                       const float* __restrict__ W) {
    __shared__ __align__(16) float As[2][BK][AS_LD];   // transposed: As[k][m]
    __shared__ __align__(16) float Bs[2][BK][BN];

    const int tid  = threadIdx.x;
    const int m0   = blockIdx.x * BM;
    const int part = blockIdx.y;

    // chunk range for this split (1250 = 8*156 + 2)
    const int q = NCHUNK / KSPLIT;
    const int r = NCHUNK % KSPLIT;
    const int cBeg = part * q + (part < r ? part : r);
    const int cEnd = cBeg + q + (part < r ? 1 : 0);

    // A loader: one row per thread, 8 floats (2x float4) per chunk
    const int arow = (m0 + tid < NN) ? (m0 + tid) : (NN - 1);
    const float* Aptr = A + (size_t)arow * NN;
    // B loader: 8x64 chunk, one float4 per thread
    const int b_row = tid >> 4;           // 0..7
    const int b_c   = (tid & 15) * 4;     // 0..60
    const float* Wptr = W + (size_t)b_row * BN + b_c;

    // compute mapping: 16x8 thread grid, 8 rows x 8 cols each
    const int tx = tid & 7;               // col group (8 cols)
    const int ty = tid >> 3;              // row group (8 rows)

    unsigned long long acc2[8][4] = {};   // 8 rows x 4 col-pairs

    // prologue: chunk cBeg
    float4 rA0 = *reinterpret_cast<const float4*>(Aptr + (size_t)cBeg * BK);
    float4 rA1 = *reinterpret_cast<const float4*>(Aptr + (size_t)cBeg * BK + 4);
    float4 rB  = *reinterpret_cast<const float4*>(Wptr + (size_t)cBeg * BK * BN);
    As[0][0][tid] = rA0.x; As[0][1][tid] = rA0.y; As[0][2][tid] = rA0.z; As[0][3][tid] = rA0.w;
    As[0][4][tid] = rA1.x; As[0][5][tid] = rA1.y; As[0][6][tid] = rA1.z; As[0][7][tid] = rA1.w;
    *reinterpret_cast<float4*>(&Bs[0][b_row][b_c]) = rB;
    __syncthreads();

    for (int c = cBeg; c < cEnd; ++c) {
        const int  buf     = (c - cBeg) & 1;
        const bool hasNext = (c + 1 < cEnd);
        if (hasNext) {
            rA0 = *reinterpret_cast<const float4*>(Aptr + (size_t)(c + 1) * BK);
            rA1 = *reinterpret_cast<const float4*>(Aptr + (size_t)(c + 1) * BK + 4);
            rB  = *reinterpret_cast<const float4*>(Wptr + (size_t)(c + 1) * BK * BN);
        }
        #pragma unroll
        for (int kk = 0; kk < BK; ++kk) {
            const float4 av0 = *reinterpret_cast<const float4*>(&As[buf][kk][ty * 8]);
            const float4 av1 = *reinterpret_cast<const float4*>(&As[buf][kk][ty * 8 + 4]);
            const float4 bv0 = *reinterpret_cast<const float4*>(&Bs[buf][kk][tx * 8]);
            const float4 bv1 = *reinterpret_cast<const float4*>(&Bs[buf][kk][tx * 8 + 4]);
            unsigned long long b2[4];
            b2[0] = pack2(bv0.x, bv0.y);
            b2[1] = pack2(bv0.z, bv0.w);
            b2[2] = pack2(bv1.x, bv1.y);
            b2[3] = pack2(bv1.z, bv1.w);
            const float a[8] = {av0.x, av0.y, av0.z, av0.w, av1.x, av1.y, av1.z, av1.w};
            #pragma unroll
            for (int i = 0; i < 8; ++i) {
                const unsigned long long a2 = pack2(a[i], a[i]);
                ffma2(acc2[i][0], a2, b2[0]);
                ffma2(acc2[i][1], a2, b2[1]);
                ffma2(acc2[i][2], a2, b2[2]);
                ffma2(acc2[i][3], a2, b2[3]);
            }
        }
        if (hasNext) {
            const int nb = buf ^ 1;
            As[nb][0][tid] = rA0.x; As[nb][1][tid] = rA0.y; As[nb][2][tid] = rA0.z; As[nb][3][tid] = rA0.w;
            As[nb][4][tid] = rA1.x; As[nb][5][tid] = rA1.y; As[nb][6][tid] = rA1.z; As[nb][7][tid] = rA1.w;
            *reinterpret_cast<float4*>(&Bs[nb][b_row][b_c]) = rB;
            __syncthreads();
        }
    }

    float* outp = &g_part[(size_t)part * NN * F1];
    #pragma unroll
    for (int i = 0; i < 8; ++i) {
        const int row = m0 + ty * 8 + i;
        if (row < NN) {
            const float2 p0 = unpack2(acc2[i][0]);
            const float2 p1 = unpack2(acc2[i][1]);
            const float2 p2 = unpack2(acc2[i][2]);
            const float2 p3 = unpack2(acc2[i][3]);
            float4 v0 = make_float4(p0.x, p0.y, p1.x, p1.y);
            float4 v1 = make_float4(p2.x, p2.y, p3.x, p3.y);
            *reinterpret_cast<float4*>(&outp[(size_t)row * F1 + tx * 8])     = v0;
            *reinterpret_cast<float4*>(&outp[(size_t)row * F1 + tx * 8 + 4]) = v1;
        }
    }
}

// reduce split-K partials -> g_bufA, and fused self-loop init -> g_bufB
__global__ void reduce_agg_kernel() {
    int idx4 = blockIdx.x * blockDim.x + threadIdx.x;   // float4 index
    if (idx4 < NN * F1 / 4) {
        float4 s = make_float4(0.f, 0.f, 0.f, 0.f);
        #pragma unroll
        for (int p = 0; p < KSPLIT; ++p) {
            const float4 v = *reinterpret_cast<const float4*>(&g_part[(size_t)p * NN * F1 + (size_t)idx4 * 4]);
            s.x += v.x; s.y += v.y; s.z += v.z; s.w += v.w;
        }
        *reinterpret_cast<float4*>(&g_bufA[(size_t)idx4 * 4]) = s;
        const int row = idx4 / (F1 / 4);
        const float d  = g_dinv[row];
        const float d2 = d * d;
        float4 t = make_float4(s.x * d2, s.y * d2, s.z * d2, s.w * d2);
        *reinterpret_cast<float4*>(&g_bufB[(size_t)idx4 * 4]) = t;
    }
}

// ---------------- small GEMMs: g_bufB [NN,64] x W [64,C] -> bufA (+init bufB)
template <int CIN, int C>
__global__ void gemm_small_agg_kernel(const float* __restrict__ W) {
    __shared__ float w_s[CIN * C];
    for (int i = threadIdx.x; i < CIN * C; i += blockDim.x) w_s[i] = W[i];
    __syncthreads();

    const int total  = NN * C;
    const int stride = gridDim.x * blockDim.x;
    for (int idx = blockIdx.x * blockDim.x + threadIdx.x; idx < total; idx += stride) {
        const int row = idx / C;
        const int col = idx % C;
        const float* rp = &g_bufB[(size_t)row * CIN];
        float acc = 0.0f;
        #pragma unroll
        for (int k = 0; k < CIN; ++k) acc += rp[k] * w_s[k * C + col];
        g_bufA[idx] = acc;
    }
}

// self-loop init (separate: gemm_small reads bufB, so bufB init must follow)
template <int C>
__global__ void agg_init_kernel() {
    int idx4 = blockIdx.x * blockDim.x + threadIdx.x;
    if (idx4 < NN * C / 4) {
        const int row = idx4 / (C / 4);
        const float d  = g_dinv[row];
        const float d2 = d * d;
        const float4 v = *reinterpret_cast<const float4*>(&g_bufA[(size_t)idx4 * 4]);
        float4 t = make_float4(v.x * d2, v.y * d2, v.z * d2, v.w * d2);
        *reinterpret_cast<float4*>(&g_bufB[(size_t)idx4 * 4]) = t;
    }
}

// edges: one thread per (edge, 4-col group): float4 gather + red.v4
template <int C>
__global__ void agg_edges_kernel(const int* __restrict__ ei, int E) {
    constexpr int LPE = C / 4;
    const long long t = (long long)blockIdx.x * blockDim.x + threadIdx.x;
    if (t >= (long long)E * LPE) return;
    const int e = (int)(t / LPE);
    const int g = (int)(t % LPE);
    const int src = clampN(ei[e]);
    const int dst = clampN(ei[E + e]);
    const float norm = g_dinv[src] * g_dinv[dst];
    const float4 v = *reinterpret_cast<const float4*>(&g_bufA[(size_t)src * C + g * 4]);
    float* o = &g_bufB[(size_t)dst * C + g * 4];
    asm volatile("red.global.add.v4.f32 [%0], {%1, %2, %3, %4};"
                 :: "l"(o), "f"(v.x * norm), "f"(v.y * norm),
                    "f"(v.z * norm), "f"(v.w * norm)
                 : "memory");
}

// ---------------- epilogues (in-place on g_bufB) ----------------
template <int C>
__global__ void bias_relu_kernel(const float* __restrict__ b) {
    int idx4 = blockIdx.x * blockDim.x + threadIdx.x;
    if (idx4 < NN * C / 4) {
        const float4 bb = *reinterpret_cast<const float4*>(&b[(idx4 % (C / 4)) * 4]);
        float4 v = *reinterpret_cast<float4*>(&g_bufB[(size_t)idx4 * 4]);
        v.x = fmaxf(v.x + bb.x, 0.f);
        v.y = fmaxf(v.y + bb.y, 0.f);
        v.z = fmaxf(v.z + bb.z, 0.f);
        v.w = fmaxf(v.w + bb.w, 0.f);
        *reinterpret_cast<float4*>(&g_bufB[(size_t)idx4 * 4]) = v;
    }
}

__global__ void softmax_kernel(const float* __restrict__ b, float* __restrict__ out) {
    int r = blockIdx.x * blockDim.x + threadIdx.x;
    if (r >= NN) return;
    float v[COUT];
    float m = -1e30f;
    #pragma unroll
    for (int j = 0; j < COUT; ++j) {
        v[j] = g_bufB[(size_t)r * COUT + j] + b[j];
        m = fmaxf(m, v[j]);
    }
    float s = 0.0f;
    #pragma unroll
    for (int j = 0; j < COUT; ++j) {
        v[j] = expf(v[j] - m);
        s += v[j];
    }
    const float inv = 1.0f / s;
    #pragma unroll
    for (int j = 0; j < COUT; ++j) out[(size_t)r * COUT + j] = v[j] * inv;
}

// ---------------- launch ----------------
extern "C" void kernel_launch(void* const* d_in, const int* in_sizes, int n_in,
                              void* d_out, int out_size) {
    const float* x  = (const float*)d_in[0];
    const int*   ei = (const int*)d_in[1];   // int32! (JAX x64 disabled)
    const float* W1 = (const float*)d_in[2];
    const float* b1 = (const float*)d_in[3];
    const float* W2 = (const float*)d_in[4];
    const float* b2 = (const float*)d_in[5];
    const float* W3 = (const float*)d_in[6];
    const float* b3 = (const float*)d_in[7];
    float* out = (float*)d_out;

    const int E = in_sizes[1] / 2;

    const int T = 256;
    const int gN    = (NN + T - 1) / T;
    const int gE    = (E + T - 1) / T;
    const int g64v  = (NN * F1 / 4 + T - 1) / T;
    const int g16v  = (NN * COUT / 4 + T - 1) / T;
    const int g64   = (NN * F1 + T - 1) / T;
    const int g16   = (NN * COUT + T - 1) / T;
    const int gE64  = (int)(((long long)E * (F1 / 4) + T - 1) / T);
    const int gE16  = (int)(((long long)E * (COUT / 4) + T - 1) / T);
    const dim3 gGemm1((NN + BM - 1) / BM, KSPLIT);   // 79 x 8

    // degrees + normalization (recomputed every call: deterministic)
    deg_init_kernel<<<gN, T>>>();
    deg_count_kernel<<<gE, T>>>(ei, E);
    dinv_kernel<<<gN, T>>>();

    // ---- layer 1 ----
    gemm1_kernel<<<gGemm1, 128>>>(x, W1);
    reduce_agg_kernel<<<g64v, T>>>();              // bufA = sum, bufB = self-loop
    agg_edges_kernel<F1><<<gE64, T>>>(ei, E);
    bias_relu_kernel<F1><<<g64v, T>>>(b1);

    // ---- layer 2 ----
    gemm_small_agg_kernel<F1, F1><<<1480, T>>>(W2);   // bufA = bufB @ W2
    agg_init_kernel<F1><<<g64v, T>>>();               // bufB = bufA * d^2
    agg_edges_kernel<F1><<<gE64, T>>>(ei, E);
    bias_relu_kernel<F1><<<g64v, T>>>(b2);

    // ---- layer 3 ----
    gemm_small_agg_kernel<F1, COUT><<<1480, T>>>(W3);
    agg_init_kernel<COUT><<<g16v, T>>>();
    agg_edges_kernel<COUT><<<gE16, T>>>(ei, E);
    softmax_kernel<<<gN, T>>>(b3, out);
}

// round 7
// speedup vs baseline: 1.3087x; 1.3087x over previous
#include <cuda_runtime.h>
#include <cstdint>

// ---------------- problem constants (fixed-shape problem) ----------------
constexpr int NN   = 10000;  // nodes
constexpr int F1   = 64;     // hidden feat
constexpr int COUT = 16;     // classes

// GEMM1 (mma.sync tf32) tiling
constexpr int BM    = 128;
constexpr int BN    = 64;
constexpr int BK    = 16;
constexpr int SPLIT = 4;
constexpr int NCH   = NN / BK;   // 625 exact -> no K tail
constexpr int LDK   = 20;        // padded k-stride (floats): (4g+t)%32 distinct

// ---------------- device scratch (no allocation; device-code refs only) --
__device__ __align__(16) float g_deg[NN];
__device__ __align__(16) float g_dinv[NN];
__device__ __align__(16) float g_bufA[(size_t)NN * F1];
__device__ __align__(16) float g_bufB[(size_t)NN * F1];
__device__ __align__(16) float g_part[(size_t)SPLIT * NN * F1];
__device__ __align__(16) float g_wt[(size_t)128 * NN];  // rows 0..63 tf32-hi(W1^T), 64..127 tf32-lo

__device__ __forceinline__ int clampN(int v) {
    v = v < 0 ? 0 : v;
    return v < NN ? v : NN - 1;
}

// ---------------- PTX helpers ----------------
__device__ __forceinline__ uint32_t tf32_rna(float f) {
    uint32_t u;
    asm("cvt.rna.tf32.f32 %0, %1;" : "=r"(u) : "f"(f));
    return u;
}
__device__ __forceinline__ void tf32split(float a, uint32_t& hi, uint32_t& lo) {
    hi = tf32_rna(a);
    lo = tf32_rna(a - __uint_as_float(hi));
}
__device__ __forceinline__ void mma8(float* d, const uint32_t* a, const uint32_t* b) {
    asm volatile(
        "mma.sync.aligned.m16n8k8.row.col.f32.tf32.tf32.f32 "
        "{%0,%1,%2,%3},{%4,%5,%6,%7},{%8,%9},{%0,%1,%2,%3};"
        : "+f"(d[0]), "+f"(d[1]), "+f"(d[2]), "+f"(d[3])
        : "r"(a[0]), "r"(a[1]), "r"(a[2]), "r"(a[3]), "r"(b[0]), "r"(b[1]));
}
__device__ __forceinline__ void cp16(uint32_t dst, const void* src) {
    asm volatile("cp.async.cg.shared.global [%0], [%1], 16;" :: "r"(dst), "l"(src));
}

// ---------------- degree / norm ----------------
__global__ void deg_init_kernel() {
    int i = blockIdx.x * blockDim.x + threadIdx.x;
    if (i < NN) g_deg[i] = 1.0f;
}
__global__ void deg_count_kernel(const int* __restrict__ ei, int E) {
    int e = blockIdx.x * blockDim.x + threadIdx.x;
    if (e < E) atomicAdd(&g_deg[clampN(ei[E + e])], 1.0f);
}
__global__ void dinv_kernel() {
    int i = blockIdx.x * blockDim.x + threadIdx.x;
    if (i < NN) g_dinv[i] = rsqrtf(g_deg[i]);
}

// ---------------- W1 transpose + tf32 hi/lo split ----------------
__global__ void transpose_w_kernel(const float* __restrict__ W) {
    __shared__ float t[64][65];
    const int tid = threadIdx.x;
    const int k0  = blockIdx.x * 64;
    for (int i = tid; i < 64 * 64; i += 256) {
        int kk = i >> 6, n = i & 63;
        t[n][kk] = (k0 + kk < NN) ? W[(size_t)(k0 + kk) * 64 + n] : 0.0f;
    }
    __syncthreads();
    for (int i = tid; i < 64 * 64; i += 256) {
        int n = i >> 6, kk = i & 63;
        if (k0 + kk < NN) {
            float w = t[n][kk];
            uint32_t hi, lo;
            tf32split(w, hi, lo);
            g_wt[(size_t)n * NN + k0 + kk]        = __uint_as_float(hi);
            g_wt[(size_t)(64 + n) * NN + k0 + kk] = __uint_as_float(lo);
        }
    }
}

// ---------------- GEMM1: mma.sync tf32 hi/lo, split-K ----------------
__global__ void __launch_bounds__(256, 2) gemm1_mma_kernel(const float* __restrict__ A) {
    __shared__ __align__(16) float As[2][BM][LDK];    // [stage][m][k]
    __shared__ __align__(16) float Bs[2][128][LDK];   // [stage][hi:0-63|lo:64-127][k]

    const int tid  = threadIdx.x;
    const int lane = tid & 31;
    const int wid  = tid >> 5;
    const int g    = lane >> 2;        // group id (0..7)
    const int t    = lane & 3;         // thread-in-group
    const int wm   = wid >> 2;         // warp m (0..1), tile 64
    const int wn   = wid & 3;          // warp n (0..3), tile 16
    const int m0   = blockIdx.x * BM;
    const int part = blockIdx.y;

    const int q = NCH / SPLIT, r = NCH % SPLIT;
    const int cBeg = part * q + (part < r ? part : r);
    const int nCh  = q + (part < r ? 1 : 0);

    // cp.async mapping: 512 A tasks + 512 B tasks; 2 each per thread
    const int lrow = tid >> 2;           // 0..63
    const int lj   = (tid & 3) * 4;      // k word offset 0,4,8,12
    const int aRow0 = clampN(m0 + lrow);
    const int aRow1 = clampN(m0 + 64 + lrow);
    const float* Ap0 = A + (size_t)aRow0 * NN + lj;
    const float* Ap1 = A + (size_t)aRow1 * NN + lj;
    const float* Bp0 = &g_wt[(size_t)lrow * NN + lj];
    const float* Bp1 = &g_wt[(size_t)(64 + lrow) * NN + lj];

    const uint32_t asb = (uint32_t)__cvta_generic_to_shared(&As[0][0][0]);
    const uint32_t bsb = (uint32_t)__cvta_generic_to_shared(&Bs[0][0][0]);
    const uint32_t aOff0 = (uint32_t)((lrow * LDK + lj) * 4);
    const uint32_t aOff1 = (uint32_t)(((64 + lrow) * LDK + lj) * 4);
    const uint32_t stageA = (uint32_t)(BM * LDK * 4);
    const uint32_t stageB = (uint32_t)(128 * LDK * 4);

    float acc[4][2][4] = {};   // [msub][nsub][reg]

    // prologue: chunk 0 -> stage 0
    {
        const size_t k0 = (size_t)cBeg * BK;
        cp16(asb + aOff0, Ap0 + k0);
        cp16(asb + aOff1, Ap1 + k0);
        cp16(bsb + aOff0, Bp0 + k0);
        cp16(bsb + aOff1, Bp1 + k0);
        asm volatile("cp.async.commit_group;");
    }

    for (int i = 0; i < nCh; ++i) {
        const int s = i & 1;
        if (i + 1 < nCh) {
            const int ns = s ^ 1;
            const size_t k0 = (size_t)(cBeg + i + 1) * BK;
            cp16(asb + ns * stageA + aOff0, Ap0 + k0);
            cp16(asb + ns * stageA + aOff1, Ap1 + k0);
            cp16(bsb + ns * stageB + aOff0, Bp0 + k0);
            cp16(bsb + ns * stageB + aOff1, Bp1 + k0);
            asm volatile("cp.async.commit_group;");
            asm volatile("cp.async.wait_group 1;");
        } else {
            asm volatile("cp.async.wait_group 0;");
        }
        __syncthreads();

        #pragma unroll
        for (int k8 = 0; k8 < 2; ++k8) {
            const int c0 = k8 * 8 + t;
            const int c1 = c0 + 4;

            uint32_t ah[4][4], al[4][4];
            #pragma unroll
            for (int ms = 0; ms < 4; ++ms) {
                const int r0 = wm * 64 + ms * 16 + g;
                const float a0 = As[s][r0][c0];
                const float a1 = As[s][r0 + 8][c0];
                const float a2 = As[s][r0][c1];
                const float a3 = As[s][r0 + 8][c1];
                tf32split(a0, ah[ms][0], al[ms][0]);
                tf32split(a1, ah[ms][1], al[ms][1]);
                tf32split(a2, ah[ms][2], al[ms][2]);
                tf32split(a3, ah[ms][3], al[ms][3]);
            }
            uint32_t bh[2][2], bl[2][2];
            #pragma unroll
            for (int ns = 0; ns < 2; ++ns) {
                const int n = wn * 16 + ns * 8 + g;
                bh[ns][0] = __float_as_uint(Bs[s][n][c0]);
                bh[ns][1] = __float_as_uint(Bs[s][n][c1]);
                bl[ns][0] = __float_as_uint(Bs[s][64 + n][c0]);
                bl[ns][1] = __float_as_uint(Bs[s][64 + n][c1]);
            }
            #pragma unroll
            for (int ms = 0; ms < 4; ++ms) {
                #pragma unroll
                for (int ns = 0; ns < 2; ++ns) {
                    mma8(acc[ms][ns], ah[ms], bh[ns]);   // hi*hi
                    mma8(acc[ms][ns], ah[ms], bl[ns]);   // hi*lo
                    mma8(acc[ms][ns], al[ms], bh[ns]);   // lo*hi
                }
            }
        }
        __syncthreads();
    }

    // epilogue -> g_part[part]
    float* outp = &g_part[(size_t)part * NN * F1];
    #pragma unroll
    for (int ms = 0; ms < 4; ++ms) {
        #pragma unroll
        for (int ns = 0; ns < 2; ++ns) {
            const int col = wn * 16 + ns * 8 + 2 * t;
            const int r0  = m0 + wm * 64 + ms * 16 + g;
            if (r0 < NN) {
                float2 v0 = make_float2(acc[ms][ns][0], acc[ms][ns][1]);
                *reinterpret_cast<float2*>(&outp[(size_t)r0 * F1 + col]) = v0;
            }
            const int r1 = r0 + 8;
            if (r1 < NN) {
                float2 v1 = make_float2(acc[ms][ns][2], acc[ms][ns][3]);
                *reinterpret_cast<float2*>(&outp[(size_t)r1 * F1 + col]) = v1;
            }
        }
    }
}

// reduce split-K partials -> g_bufA, fused self-loop init -> g_bufB
__global__ void reduce_agg_kernel() {
    int idx4 = blockIdx.x * blockDim.x + threadIdx.x;
    if (idx4 < NN * F1 / 4) {
        float4 s = make_float4(0.f, 0.f, 0.f, 0.f);
        #pragma unroll
        for (int p = 0; p < SPLIT; ++p) {
            const float4 v = *reinterpret_cast<const float4*>(
                &g_part[(size_t)p * NN * F1 + (size_t)idx4 * 4]);
            s.x += v.x; s.y += v.y; s.z += v.z; s.w += v.w;
        }
        *reinterpret_cast<float4*>(&g_bufA[(size_t)idx4 * 4]) = s;
        const int row = idx4 / (F1 / 4);
        const float d  = g_dinv[row];
        const float d2 = d * d;
        float4 tt = make_float4(s.x * d2, s.y * d2, s.z * d2, s.w * d2);
        *reinterpret_cast<float4*>(&g_bufB[(size_t)idx4 * 4]) = tt;
    }
}

// ---------------- small GEMMs: g_bufB [NN,64] x W [64,C] -> g_bufA --------
template <int CIN, int C>
__global__ void gemm_small_agg_kernel(const float* __restrict__ W) {
    __shared__ float w_s[CIN * C];
    for (int i = threadIdx.x; i < CIN * C; i += blockDim.x) w_s[i] = W[i];
    __syncthreads();
    const int total  = NN * C;
    const int stride = gridDim.x * blockDim.x;
    for (int idx = blockIdx.x * blockDim.x + threadIdx.x; idx < total; idx += stride) {
        const int row = idx / C;
        const int col = idx % C;
        const float* rp = &g_bufB[(size_t)row * CIN];
        float acc = 0.0f;
        #pragma unroll
        for (int k = 0; k < CIN; ++k) acc += rp[k] * w_s[k * C + col];
        g_bufA[idx] = acc;
    }
}

// self-loop init for layers 2/3
template <int C>
__global__ void agg_init_kernel() {
    int idx4 = blockIdx.x * blockDim.x + threadIdx.x;
    if (idx4 < NN * C / 4) {
        const int row = idx4 / (C / 4);
        const float d  = g_dinv[row];
        const float d2 = d * d;
        const float4 v = *reinterpret_cast<const float4*>(&g_bufA[(size_t)idx4 * 4]);
        float4 tt = make_float4(v.x * d2, v.y * d2, v.z * d2, v.w * d2);
        *reinterpret_cast<float4*>(&g_bufB[(size_t)idx4 * 4]) = tt;
    }
}

// edges: one thread per (edge, 4-col group): float4 gather + red.v4
template <int C>
__global__ void agg_edges_kernel(const int* __restrict__ ei, int E) {
    constexpr int LPE = C / 4;
    const long long t = (long long)blockIdx.x * blockDim.x + threadIdx.x;
    if (t >= (long long)E * LPE) return;
    const int e = (int)(t / LPE);
    const int g = (int)(t % LPE);
    const int src = clampN(ei[e]);
    const int dst = clampN(ei[E + e]);
    const float norm = g_dinv[src] * g_dinv[dst];
    const float4 v = *reinterpret_cast<const float4*>(&g_bufA[(size_t)src * C + g * 4]);
    float* o = &g_bufB[(size_t)dst * C + g * 4];
    asm volatile("red.global.add.v4.f32 [%0], {%1, %2, %3, %4};"
                 :: "l"(o), "f"(v.x * norm), "f"(v.y * norm),
                    "f"(v.z * norm), "f"(v.w * norm)
                 : "memory");
}

// ---------------- epilogues ----------------
template <int C>
__global__ void bias_relu_kernel(const float* __restrict__ b) {
    int idx4 = blockIdx.x * blockDim.x + threadIdx.x;
    if (idx4 < NN * C / 4) {
        const float4 bb = *reinterpret_cast<const float4*>(&b[(idx4 % (C / 4)) * 4]);
        float4 v = *reinterpret_cast<float4*>(&g_bufB[(size_t)idx4 * 4]);
        v.x = fmaxf(v.x + bb.x, 0.f);
        v.y = fmaxf(v.y + bb.y, 0.f);
        v.z = fmaxf(v.z + bb.z, 0.f);
        v.w = fmaxf(v.w + bb.w, 0.f);
        *reinterpret_cast<float4*>(&g_bufB[(size_t)idx4 * 4]) = v;
    }
}

__global__ void softmax_kernel(const float* __restrict__ b, float* __restrict__ out) {
    int r = blockIdx.x * blockDim.x + threadIdx.x;
    if (r >= NN) return;
    float v[COUT];
    float m = -1e30f;
    #pragma unroll
    for (int j = 0; j < COUT; ++j) {
        v[j] = g_bufB[(size_t)r * COUT + j] + b[j];
        m = fmaxf(m, v[j]);
    }
    float s = 0.0f;
    #pragma unroll
    for (int j = 0; j < COUT; ++j) {
        v[j] = expf(v[j] - m);
        s += v[j];
    }
    const float inv = 1.0f / s;
    #pragma unroll
    for (int j = 0; j < COUT; ++j) out[(size_t)r * COUT + j] = v[j] * inv;
}

// ---------------- launch ----------------
extern "C" void kernel_launch(void* const* d_in, const int* in_sizes, int n_in,
                              void* d_out, int out_size) {
    const float* x  = (const float*)d_in[0];
    const int*   ei = (const int*)d_in[1];   // int32 (JAX x64 disabled)
    const float* W1 = (const float*)d_in[2];
    const float* b1 = (const float*)d_in[3];
    const float* W2 = (const float*)d_in[4];
    const float* b2 = (const float*)d_in[5];
    const float* W3 = (const float*)d_in[6];
    const float* b3 = (const float*)d_in[7];
    float* out = (float*)d_out;

    const int E = in_sizes[1] / 2;

    const int T = 256;
    const int gN    = (NN + T - 1) / T;
    const int gE    = (E + T - 1) / T;
    const int g64v  = (NN * F1 / 4 + T - 1) / T;
    const int g16v  = (NN * COUT / 4 + T - 1) / T;
    const int gE64  = (int)(((long long)E * (F1 / 4) + T - 1) / T);
    const int gE16  = (int)(((long long)E * (COUT / 4) + T - 1) / T);
    const dim3 gG((NN + BM - 1) / BM, SPLIT);   // 79 x 4

    // degrees + normalization + W1 prep
    deg_init_kernel<<<gN, T>>>();
    deg_count_kernel<<<gE, T>>>(ei, E);
    dinv_kernel<<<gN, T>>>();
    transpose_w_kernel<<<(NN + 63) / 64, 256>>>(W1);

    // ---- layer 1 ----
    gemm1_mma_kernel<<<gG, 256>>>(x);
    reduce_agg_kernel<<<g64v, T>>>();              // bufA = sum parts, bufB = self-loop
    agg_edges_kernel<F1><<<gE64, T>>>(ei, E);
    bias_relu_kernel<F1><<<g64v, T>>>(b1);

    // ---- layer 2 ----
    gemm_small_agg_kernel<F1, F1><<<1480, T>>>(W2);
    agg_init_kernel<F1><<<g64v, T>>>();
    agg_edges_kernel<F1><<<gE64, T>>>(ei, E);
    bias_relu_kernel<F1><<<g64v, T>>>(b2);

    // ---- layer 3 ----
    gemm_small_agg_kernel<F1, COUT><<<1480, T>>>(W3);
    agg_init_kernel<COUT><<<g16v, T>>>();
    agg_edges_kernel<COUT><<<gE16, T>>>(ei, E);
    softmax_kernel<<<gN, T>>>(b3, out);
}